// round 1
// baseline (speedup 1.0000x reference)
#include <cuda_runtime.h>
#include <math.h>

// Problem constants
#define BATCH 2
#define C 512
#define NTOK 4096            // 16*16*16
#define GROUPS 32
#define CPG 16               // C / GROUPS
#define CN (C * NTOK)        // per-batch hn/q/k/v/o size
#define NN ((long)NTOK * NTOK)

// ---------------- scratch (device globals; no allocations allowed) ------------
__device__ float g_hn[(long)BATCH * CN];
__device__ float g_q [(long)BATCH * CN];
__device__ float g_k [(long)BATCH * CN];
__device__ float g_v [(long)BATCH * CN];
__device__ float g_o [(long)BATCH * CN];
__device__ float g_s [(long)BATCH * NN];   // attention scores / probs (128 MB)

// ---------------- GroupNorm ---------------------------------------------------
// One block per (group, batch). Stats over CPG*NTOK = 65536 elements.
__global__ void __launch_bounds__(256) groupnorm_kernel(
    const float* __restrict__ x, const float* __restrict__ w,
    const float* __restrict__ b, float* __restrict__ hn)
{
    const int g  = blockIdx.x;
    const int bb = blockIdx.y;
    const long base = ((long)bb * C + (long)g * CPG) * NTOK;
    const int total = CPG * NTOK;

    float s = 0.f, s2 = 0.f;
    for (int i = threadIdx.x; i < total; i += 256) {
        float v = x[base + i];
        s += v; s2 += v * v;
    }
    __shared__ float rs[256], rs2[256];
    rs[threadIdx.x] = s; rs2[threadIdx.x] = s2;
    __syncthreads();
    for (int off = 128; off > 0; off >>= 1) {
        if (threadIdx.x < off) {
            rs[threadIdx.x]  += rs[threadIdx.x + off];
            rs2[threadIdx.x] += rs2[threadIdx.x + off];
        }
        __syncthreads();
    }
    const float mean = rs[0] / (float)total;
    const float var  = rs2[0] / (float)total - mean * mean;
    const float rstd = rsqrtf(var + 1e-6f);

    for (int i = threadIdx.x; i < total; i += 256) {
        int c = g * CPG + i / NTOK;
        hn[base + i] = (x[base + i] - mean) * rstd * w[c] + b[c];
    }
}

// ---------------- generic batched SGEMM --------------------------------------
// C[m,n] = scale * sum_k A(m,k) * B(k,n) + bias[m] + R[m,n]
// AT: A stored as A[k*lda + m] (m-contiguous), else A[m*lda + k]
// BT: B stored as B[n*ldb + k] (k-contiguous), else B[k*ldb + n]
// Tiles: 128x128x16, 256 threads, 8x8 per thread. M,N % 128 == 0, K % 16 == 0.
#define BM 128
#define BN 128
#define BK 16

template <bool AT, bool BT>
__global__ void __launch_bounds__(256) gemm_kernel(
    const float* __restrict__ A, const float* __restrict__ B,
    float* __restrict__ Cmat, int K, int lda, int ldb, int ldc,
    long sA, long sB, long sC,
    const float* __restrict__ bias, float scale,
    const float* __restrict__ R, long sR)
{
    const int bz = blockIdx.z;
    A += (long)bz * sA;
    B += (long)bz * sB;
    Cmat += (long)bz * sC;
    if (R) R += (long)bz * sR;

    const int m0 = blockIdx.y * BM;
    const int n0 = blockIdx.x * BN;

    __shared__ float As[BK][BM];
    __shared__ float Bs[BK][BN];

    const int tid = threadIdx.x;
    const int tx = tid & 15;        // 0..15 -> n
    const int ty = tid >> 4;        // 0..15 -> m

    float acc[8][8];
#pragma unroll
    for (int i = 0; i < 8; i++)
#pragma unroll
        for (int j = 0; j < 8; j++) acc[i][j] = 0.f;

    for (int k0 = 0; k0 < K; k0 += BK) {
        // load A tile
#pragma unroll
        for (int i = 0; i < (BM * BK) / 256; i++) {
            int t = tid + i * 256;
            if (AT) {
                int k = t / BM, m = t % BM;
                As[k][m] = A[(long)(k0 + k) * lda + (m0 + m)];
            } else {
                int m = t / BK, k = t % BK;
                As[k][m] = A[(long)(m0 + m) * lda + (k0 + k)];
            }
        }
        // load B tile
#pragma unroll
        for (int i = 0; i < (BN * BK) / 256; i++) {
            int t = tid + i * 256;
            if (BT) {
                int n = t / BK, k = t % BK;
                Bs[k][n] = B[(long)(n0 + n) * ldb + (k0 + k)];
            } else {
                int k = t / BN, n = t % BN;
                Bs[k][n] = B[(long)(k0 + k) * ldb + (n0 + n)];
            }
        }
        __syncthreads();

#pragma unroll
        for (int k = 0; k < BK; k++) {
            float a[8], bb[8];
#pragma unroll
            for (int i = 0; i < 8; i++) a[i] = As[k][ty * 8 + i];
#pragma unroll
            for (int j = 0; j < 8; j++) bb[j] = Bs[k][tx * 8 + j];
#pragma unroll
            for (int i = 0; i < 8; i++)
#pragma unroll
                for (int j = 0; j < 8; j++) acc[i][j] += a[i] * bb[j];
        }
        __syncthreads();
    }

#pragma unroll
    for (int i = 0; i < 8; i++) {
        const int m = m0 + ty * 8 + i;
        const float bv = bias ? bias[m] : 0.f;
#pragma unroll
        for (int j = 0; j < 8; j++) {
            const int n = n0 + tx * 8 + j;
            float v = acc[i][j] * scale + bv;
            if (R) v += R[(long)m * ldc + n];
            Cmat[(long)m * ldc + n] = v;
        }
    }
}

// ---------------- row softmax over 4096 --------------------------------------
__global__ void __launch_bounds__(256) softmax_kernel(float* __restrict__ S)
{
    const long row = (long)blockIdx.y * gridDim.x + blockIdx.x;  // b*NTOK + i
    float* p = S + row * NTOK;
    const int tid = threadIdx.x;

    float vals[16];
    float mx = -1e30f;
#pragma unroll
    for (int i = 0; i < 16; i++) {
        vals[i] = p[tid + i * 256];
        mx = fmaxf(mx, vals[i]);
    }

    __shared__ float sm[32];
    // block max
#pragma unroll
    for (int o = 16; o > 0; o >>= 1) mx = fmaxf(mx, __shfl_xor_sync(0xffffffffu, mx, o));
    if ((tid & 31) == 0) sm[tid >> 5] = mx;
    __syncthreads();
    if (tid < 32) {
        float v = (tid < 8) ? sm[tid] : -1e30f;
#pragma unroll
        for (int o = 4; o > 0; o >>= 1) v = fmaxf(v, __shfl_xor_sync(0xffffffffu, v, o));
        if (tid == 0) sm[0] = v;
    }
    __syncthreads();
    mx = sm[0];
    __syncthreads();

    float sum = 0.f;
#pragma unroll
    for (int i = 0; i < 16; i++) {
        vals[i] = expf(vals[i] - mx);
        sum += vals[i];
    }
    // block sum
#pragma unroll
    for (int o = 16; o > 0; o >>= 1) sum += __shfl_xor_sync(0xffffffffu, sum, o);
    if ((tid & 31) == 0) sm[tid >> 5] = sum;
    __syncthreads();
    if (tid < 32) {
        float v = (tid < 8) ? sm[tid] : 0.f;
#pragma unroll
        for (int o = 4; o > 0; o >>= 1) v += __shfl_xor_sync(0xffffffffu, v, o);
        if (tid == 0) sm[0] = v;
    }
    __syncthreads();
    const float inv = 1.f / sm[0];
#pragma unroll
    for (int i = 0; i < 16; i++) p[tid + i * 256] = vals[i] * inv;
}

// ---------------- launcher ----------------------------------------------------
extern "C" void kernel_launch(void* const* d_in, const int* in_sizes, int n_in,
                              void* d_out, int out_size)
{
    const float* x    = (const float*)d_in[0];
    const float* gn_w = (const float*)d_in[1];
    const float* gn_b = (const float*)d_in[2];
    const float* wq   = (const float*)d_in[3];
    const float* bq   = (const float*)d_in[4];
    const float* wk   = (const float*)d_in[5];
    const float* bk   = (const float*)d_in[6];
    const float* wv   = (const float*)d_in[7];
    const float* bv   = (const float*)d_in[8];
    const float* wp   = (const float*)d_in[9];
    const float* bp   = (const float*)d_in[10];
    float* out = (float*)d_out;

    float *hn, *q, *k, *v, *o, *s;
    cudaGetSymbolAddress((void**)&hn, g_hn);
    cudaGetSymbolAddress((void**)&q,  g_q);
    cudaGetSymbolAddress((void**)&k,  g_k);
    cudaGetSymbolAddress((void**)&v,  g_v);
    cudaGetSymbolAddress((void**)&o,  g_o);
    cudaGetSymbolAddress((void**)&s,  g_s);

    // 1. GroupNorm
    groupnorm_kernel<<<dim3(GROUPS, BATCH), 256>>>(x, gn_w, gn_b, hn);

    // 2. Q/K/V projections: [512x512] @ [512x4096] per batch
    {
        dim3 grid(NTOK / BN, C / BM, BATCH);
        gemm_kernel<false, false><<<grid, 256>>>(wq, hn, q, C, C, NTOK, NTOK,
                                                 0, CN, CN, bq, 1.f, nullptr, 0);
        gemm_kernel<false, false><<<grid, 256>>>(wk, hn, k, C, C, NTOK, NTOK,
                                                 0, CN, CN, bk, 1.f, nullptr, 0);
        gemm_kernel<false, false><<<grid, 256>>>(wv, hn, v, C, C, NTOK, NTOK,
                                                 0, CN, CN, bv, 1.f, nullptr, 0);
    }

    // 3. scores[i,j] = (1/sqrt(C)) * sum_c q[c,i] k[c,j]   (A transposed)
    {
        dim3 grid(NTOK / BN, NTOK / BM, BATCH);
        const float scale = 0.044194173824159216f; // 512^-0.5
        gemm_kernel<true, false><<<grid, 256>>>(q, k, s, C, NTOK, NTOK, NTOK,
                                                CN, CN, NN, nullptr, scale,
                                                nullptr, 0);
    }

    // 4. softmax over j (rows of length 4096)
    softmax_kernel<<<dim3(NTOK, BATCH), 256>>>(s);

    // 5. o[c,i] = sum_j v[c,j] * attn[i,j]   (B transposed)
    {
        dim3 grid(NTOK / BN, C / BM, BATCH);
        gemm_kernel<false, true><<<grid, 256>>>(v, s, o, NTOK, NTOK, NTOK, NTOK,
                                                CN, NN, CN, nullptr, 1.f,
                                                nullptr, 0);
    }

    // 6. out = x + wp @ o + bp
    {
        dim3 grid(NTOK / BN, C / BM, BATCH);
        gemm_kernel<false, false><<<grid, 256>>>(wp, o, out, C, C, NTOK, NTOK,
                                                 0, CN, CN, bp, 1.f, x, CN);
    }
}